// round 15
// baseline (speedup 1.0000x reference)
#include <cuda_runtime.h>
#include <cuda_device_runtime_api.h>

#define N 384
#define D 512
#define MARGIN 0.5f
#define EPS 1e-6f
#define BLK 384
#define NWARP (BLK / 32)

// Per-anchor partial contributions. Written by plain STG in kernel 1, read by
// kernel 2 after cudaGridDependencySynchronize() (PDL ordering).
__device__ float g_part[N];

__device__ __forceinline__ float warp_sum(float v) {
#pragma unroll
    for (int o = 16; o; o >>= 1) v += __shfl_xor_sync(0xffffffffu, v, o);
    return v;
}

__global__ __launch_bounds__(BLK) void triplet_main_kernel(
    const float* __restrict__ features,
    const int*   __restrict__ labels,
    const int*   __restrict__ levels) {
    __shared__ int   s_list[N];      // [0..npos) positives, [npos..npos+nneg) negatives
    __shared__ float s_distc[N];     // distance per compacted ordinal
    __shared__ int   s_wpos[NWARP];
    __shared__ int   s_wneg[NWARP];

    const int i    = blockIdx.x;
    const int t    = threadIdx.x;
    const int wid  = t >> 5;
    const int lane = t & 31;

    // Anchor row -> registers FIRST: overlaps the fetch with label loads,
    // ballots and both compaction barriers. L1-broadcast across warps.
    const float4* __restrict__ fi = (const float4*)(features + i * D);
    const float4 a0 = fi[lane];
    const float4 a1 = fi[32 + lane];
    const float4 a2 = fi[64 + lane];
    const float4 a3 = fi[96 + lane];

    const int lab_i = labels[i];     // broadcast: one L2 transaction
    const int lev_i = levels[i];
    const int lab_t = labels[t];     // coalesced
    const int lev_t = levels[t];

    const bool same   = (t != i) && (lab_t == lab_i);
    const bool is_pos = same && (lev_t == lev_i);
    const bool is_neg = same && !is_pos;

    const unsigned bal_pos = __ballot_sync(0xffffffffu, is_pos);
    const unsigned bal_neg = __ballot_sync(0xffffffffu, is_neg);
    if (lane == 0) {
        s_wpos[wid] = __popc(bal_pos);
        s_wneg[wid] = __popc(bal_neg);
    }
    __syncthreads();

    // Register prefix over 12 warp counts (paid once).
    int base_p = 0, base_n = 0, npos = 0, nneg = 0;
#pragma unroll
    for (int w = 0; w < NWARP; w++) {
        const int cp = s_wpos[w], cn = s_wneg[w];
        if (w < wid) { base_p += cp; base_n += cn; }
        npos += cp;
        nneg += cn;
    }
    if (is_pos) s_list[base_p + __popc(bal_pos & ((1u << lane) - 1u))] = t;
    if (is_neg) s_list[npos + base_n + __popc(bal_neg & ((1u << lane) - 1u))] = t;
    __syncthreads();

    // ---- distances: warps round-robin over the compacted list (balanced) ----
    const int nsame = npos + nneg;
    for (int m = wid; m < nsame; m += NWARP) {
        const int j = s_list[m];
        const float4* __restrict__ fj = (const float4*)(features + j * D);
        const float4 b0 = fj[lane];
        const float4 b1 = fj[32 + lane];
        const float4 b2 = fj[64 + lane];
        const float4 b3 = fj[96 + lane];

        float acc = 0.0f, d;
        d = a0.x - b0.x + EPS; acc = fmaf(d, d, acc);   // torch eps convention
        d = a0.y - b0.y + EPS; acc = fmaf(d, d, acc);
        d = a0.z - b0.z + EPS; acc = fmaf(d, d, acc);
        d = a0.w - b0.w + EPS; acc = fmaf(d, d, acc);
        d = a1.x - b1.x + EPS; acc = fmaf(d, d, acc);
        d = a1.y - b1.y + EPS; acc = fmaf(d, d, acc);
        d = a1.z - b1.z + EPS; acc = fmaf(d, d, acc);
        d = a1.w - b1.w + EPS; acc = fmaf(d, d, acc);
        d = a2.x - b2.x + EPS; acc = fmaf(d, d, acc);
        d = a2.y - b2.y + EPS; acc = fmaf(d, d, acc);
        d = a2.z - b2.z + EPS; acc = fmaf(d, d, acc);
        d = a2.w - b2.w + EPS; acc = fmaf(d, d, acc);
        d = a3.x - b3.x + EPS; acc = fmaf(d, d, acc);
        d = a3.y - b3.y + EPS; acc = fmaf(d, d, acc);
        d = a3.z - b3.z + EPS; acc = fmaf(d, d, acc);
        d = a3.w - b3.w + EPS; acc = fmaf(d, d, acc);
        acc = warp_sum(acc);
        if (lane == 0) s_distc[m] = sqrtf(acc);
    }
    __syncthreads();

    // ---- warp 0: full hinge (npos*nneg terms) + plain store of partial ----
    if (wid == 0) {
        float acc = 0.0f;
        const int npair = npos * nneg;
        for (int p = lane; p < npair; p += 32) {
            const int a = p / nneg;          // positive ordinal
            const int q = p - a * nneg;      // negative ordinal
            acc += fmaxf(s_distc[a] - s_distc[npos + q] + MARGIN, 0.0f);
        }
        acc = warp_sum(acc);
        if (lane == 0) {
            float contrib = 0.0f;
            if (npair > 0) contrib = acc / (float)npair * (1.0f / (float)N);
            g_part[i] = contrib;             // plain STG — no fence, no atomic
        }
    }

    // Signal PDL completion: the dependent kernel's grid-sync releases once
    // every CTA has triggered (after its g_part store) or exited.
    cudaTriggerProgrammaticLaunchCompletion();
}

// One block: reduce the 384 partials and write the scalar output. Launched
// with programmatic-stream-serialization so its prologue overlaps kernel 1.
__global__ __launch_bounds__(BLK) void triplet_reduce_kernel(float* __restrict__ out) {
    __shared__ float s_w[NWARP];
    const int t    = threadIdx.x;
    const int wid  = t >> 5;
    const int lane = t & 31;

    cudaGridDependencySynchronize();   // wait for main kernel's memory

    float v = warp_sum(g_part[t]);
    if (lane == 0) s_w[wid] = v;
    __syncthreads();

    if (wid == 0) {
        float x = (lane < NWARP) ? s_w[lane] : 0.0f;
#pragma unroll
        for (int o = 8; o; o >>= 1) x += __shfl_xor_sync(0xffffffffu, x, o);
        if (lane == 0) out[0] = x;
    }
}

extern "C" void kernel_launch(void* const* d_in, const int* in_sizes, int n_in,
                              void* d_out, int out_size) {
    const float* features = (const float*)d_in[0];
    const int*   labels   = (const int*)d_in[1];
    const int*   levels   = (const int*)d_in[2];
    float* out = (float*)d_out;

    triplet_main_kernel<<<N, BLK>>>(features, labels, levels);

    // PDL: allow the reduce kernel to launch before the main kernel retires;
    // cudaGridDependencySynchronize() inside gates the data dependency.
    cudaLaunchConfig_t cfg = {};
    cfg.gridDim  = dim3(1, 1, 1);
    cfg.blockDim = dim3(BLK, 1, 1);
    cfg.dynamicSmemBytes = 0;
    cfg.stream = 0;
    cudaLaunchAttribute attr[1];
    attr[0].id = cudaLaunchAttributeProgrammaticStreamSerialization;
    attr[0].val.programmaticStreamSerializationAllowed = 1;
    cfg.attrs = attr;
    cfg.numAttrs = 1;
    cudaLaunchKernelEx(&cfg, triplet_reduce_kernel, out);
}

// round 16
// speedup vs baseline: 1.0956x; 1.0956x over previous
#include <cuda_runtime.h>

#define N 384
#define D 512
#define MARGIN 0.5f
#define EPS 1e-6f
#define BLK 384
#define NWARP (BLK / 32)

#define CNT_SHIFT 54                       // arrival counter lives in bits [54..63]
#define SUM_MASK  ((1ull << CNT_SHIFT) - 1ull)
#define FIX_SCALE 4294967296.0             // 2^32 fixed-point scale

// Single accumulator word: bits[54..63] = arrival count, bits[0..53] = fixed-
// point sum. Zero-initialized at load; the last block resets it each launch.
__device__ unsigned long long g_acc64;

__device__ __forceinline__ float warp_sum(float v) {
#pragma unroll
    for (int o = 16; o; o >>= 1) v += __shfl_xor_sync(0xffffffffu, v, o);
    return v;
}

__global__ __launch_bounds__(BLK) void triplet_fused_kernel(
    const float* __restrict__ features,
    const int*   __restrict__ labels,
    const int*   __restrict__ levels,
    float*       __restrict__ out) {
    __shared__ int   s_list[N];      // [0..npos) positives, [npos..npos+nneg) negatives
    __shared__ float s_distc[N];     // distance per compacted ordinal
    __shared__ int   s_wpos[NWARP];
    __shared__ int   s_wneg[NWARP];

    const int i    = blockIdx.x;
    const int t    = threadIdx.x;
    const int wid  = t >> 5;
    const int lane = t & 31;

    // Anchor row -> registers FIRST: overlaps the fetch with label loads,
    // ballots and both compaction barriers. L1-broadcast across warps.
    const float4* __restrict__ fi = (const float4*)(features + i * D);
    const float4 a0 = fi[lane];
    const float4 a1 = fi[32 + lane];
    const float4 a2 = fi[64 + lane];
    const float4 a3 = fi[96 + lane];

    const int lab_i = labels[i];     // broadcast: one L2 transaction
    const int lev_i = levels[i];
    const int lab_t = labels[t];     // coalesced
    const int lev_t = levels[t];

    const bool same   = (t != i) && (lab_t == lab_i);
    const bool is_pos = same && (lev_t == lev_i);
    const bool is_neg = same && !is_pos;

    const unsigned bal_pos = __ballot_sync(0xffffffffu, is_pos);
    const unsigned bal_neg = __ballot_sync(0xffffffffu, is_neg);
    if (lane == 0) {
        s_wpos[wid] = __popc(bal_pos);
        s_wneg[wid] = __popc(bal_neg);
    }
    __syncthreads();

    // Register prefix over 12 warp counts (paid once).
    int base_p = 0, base_n = 0, npos = 0, nneg = 0;
#pragma unroll
    for (int w = 0; w < NWARP; w++) {
        const int cp = s_wpos[w], cn = s_wneg[w];
        if (w < wid) { base_p += cp; base_n += cn; }
        npos += cp;
        nneg += cn;
    }
    if (is_pos) s_list[base_p + __popc(bal_pos & ((1u << lane) - 1u))] = t;
    if (is_neg) s_list[npos + base_n + __popc(bal_neg & ((1u << lane) - 1u))] = t;
    __syncthreads();

    // ---- distances: warps round-robin over the compacted list (balanced) ----
    const int nsame = npos + nneg;
    for (int m = wid; m < nsame; m += NWARP) {
        const int j = s_list[m];
        const float4* __restrict__ fj = (const float4*)(features + j * D);
        const float4 b0 = fj[lane];
        const float4 b1 = fj[32 + lane];
        const float4 b2 = fj[64 + lane];
        const float4 b3 = fj[96 + lane];

        float acc = 0.0f, d;
        d = a0.x - b0.x + EPS; acc = fmaf(d, d, acc);   // torch eps convention
        d = a0.y - b0.y + EPS; acc = fmaf(d, d, acc);
        d = a0.z - b0.z + EPS; acc = fmaf(d, d, acc);
        d = a0.w - b0.w + EPS; acc = fmaf(d, d, acc);
        d = a1.x - b1.x + EPS; acc = fmaf(d, d, acc);
        d = a1.y - b1.y + EPS; acc = fmaf(d, d, acc);
        d = a1.z - b1.z + EPS; acc = fmaf(d, d, acc);
        d = a1.w - b1.w + EPS; acc = fmaf(d, d, acc);
        d = a2.x - b2.x + EPS; acc = fmaf(d, d, acc);
        d = a2.y - b2.y + EPS; acc = fmaf(d, d, acc);
        d = a2.z - b2.z + EPS; acc = fmaf(d, d, acc);
        d = a2.w - b2.w + EPS; acc = fmaf(d, d, acc);
        d = a3.x - b3.x + EPS; acc = fmaf(d, d, acc);
        d = a3.y - b3.y + EPS; acc = fmaf(d, d, acc);
        d = a3.z - b3.z + EPS; acc = fmaf(d, d, acc);
        d = a3.w - b3.w + EPS; acc = fmaf(d, d, acc);
        acc = warp_sum(acc);
        if (lane == 0) s_distc[m] = sqrtf(acc);
    }
    __syncthreads();

    // ---- warp 0: full hinge (npos*nneg terms) + one-atomic finalize ----
    if (wid == 0) {
        float acc = 0.0f;
        const int npair = npos * nneg;
        for (int p = lane; p < npair; p += 32) {
            const int a = p / nneg;          // positive ordinal
            const int q = p - a * nneg;      // negative ordinal
            acc += fmaxf(s_distc[a] - s_distc[npos + q] + MARGIN, 0.0f);
        }
        acc = warp_sum(acc);

        if (lane == 0) {
            float contrib = 0.0f;
            if (npair > 0) contrib = acc / (float)npair * (1.0f / (float)N);

            // Fixed-point contribution + arrival count in ONE atomic.
            const unsigned long long fix =
                (unsigned long long)((double)contrib * FIX_SCALE + 0.5);
            const unsigned long long add = (1ull << CNT_SHIFT) + fix;
            const unsigned long long old = atomicAdd(&g_acc64, add);

            if ((old >> CNT_SHIFT) == (unsigned long long)(N - 1)) {
                // Last arrival: old + own add == complete total.
                const unsigned long long total = (old + add) & SUM_MASK;
                out[0] = (float)((double)total * (1.0 / FIX_SCALE));
                g_acc64 = 0ull;   // plain store; launch boundary orders replays
            }
        }
    }
}

extern "C" void kernel_launch(void* const* d_in, const int* in_sizes, int n_in,
                              void* d_out, int out_size) {
    const float* features = (const float*)d_in[0];
    const int*   labels   = (const int*)d_in[1];
    const int*   levels   = (const int*)d_in[2];
    float* out = (float*)d_out;

    triplet_fused_kernel<<<N, BLK>>>(features, labels, levels, out);
}

// round 17
// speedup vs baseline: 1.0996x; 1.0037x over previous
#include <cuda_runtime.h>

#define N 384
#define D 512
#define MARGIN 0.5f
#define EPS 1e-6f
#define BLK 384
#define NWARP (BLK / 32)

#define NSLOT 8
#define SLOT_PAD 16                        // 16 x 8B = 128B: one L2 line per slot
#define BLOCKS_PER_SLOT (N / NSLOT)        // 48

#define CNT_SHIFT 54                       // arrival counter in bits [54..63]
#define SUM_MASK  ((1ull << CNT_SHIFT) - 1ull)
#define FIX_SCALE 4294967296.0             // 2^32 fixed-point scale

// Two-level accumulator, all (count<<54 | fixed-point sum). Zero-initialized
// at load; the final winner resets everything each launch.
__device__ unsigned long long g_slot[NSLOT * SLOT_PAD];
__device__ unsigned long long g_final;

__device__ __forceinline__ float warp_sum(float v) {
#pragma unroll
    for (int o = 16; o; o >>= 1) v += __shfl_xor_sync(0xffffffffu, v, o);
    return v;
}

__global__ __launch_bounds__(BLK) void triplet_fused_kernel(
    const float* __restrict__ features,
    const int*   __restrict__ labels,
    const int*   __restrict__ levels,
    float*       __restrict__ out) {
    __shared__ int   s_list[N];      // [0..npos) positives, [npos..npos+nneg) negatives
    __shared__ float s_distc[N];     // distance per compacted ordinal
    __shared__ int   s_wpos[NWARP];
    __shared__ int   s_wneg[NWARP];

    const int i    = blockIdx.x;
    const int t    = threadIdx.x;
    const int wid  = t >> 5;
    const int lane = t & 31;

    // Anchor row -> registers FIRST: overlaps the fetch with label loads,
    // ballots and both compaction barriers. L1-broadcast across warps.
    const float4* __restrict__ fi = (const float4*)(features + i * D);
    const float4 a0 = fi[lane];
    const float4 a1 = fi[32 + lane];
    const float4 a2 = fi[64 + lane];
    const float4 a3 = fi[96 + lane];

    const int lab_i = labels[i];     // broadcast: one L2 transaction
    const int lev_i = levels[i];
    const int lab_t = labels[t];     // coalesced
    const int lev_t = levels[t];

    const bool same   = (t != i) && (lab_t == lab_i);
    const bool is_pos = same && (lev_t == lev_i);
    const bool is_neg = same && !is_pos;

    const unsigned bal_pos = __ballot_sync(0xffffffffu, is_pos);
    const unsigned bal_neg = __ballot_sync(0xffffffffu, is_neg);
    if (lane == 0) {
        s_wpos[wid] = __popc(bal_pos);
        s_wneg[wid] = __popc(bal_neg);
    }
    __syncthreads();

    // Register prefix over 12 warp counts (paid once).
    int base_p = 0, base_n = 0, npos = 0, nneg = 0;
#pragma unroll
    for (int w = 0; w < NWARP; w++) {
        const int cp = s_wpos[w], cn = s_wneg[w];
        if (w < wid) { base_p += cp; base_n += cn; }
        npos += cp;
        nneg += cn;
    }
    if (is_pos) s_list[base_p + __popc(bal_pos & ((1u << lane) - 1u))] = t;
    if (is_neg) s_list[npos + base_n + __popc(bal_neg & ((1u << lane) - 1u))] = t;
    __syncthreads();

    // ---- distances: warps round-robin over the compacted list (balanced) ----
    const int nsame = npos + nneg;
    for (int m = wid; m < nsame; m += NWARP) {
        const int j = s_list[m];
        const float4* __restrict__ fj = (const float4*)(features + j * D);
        const float4 b0 = fj[lane];
        const float4 b1 = fj[32 + lane];
        const float4 b2 = fj[64 + lane];
        const float4 b3 = fj[96 + lane];

        float acc = 0.0f, d;
        d = a0.x - b0.x + EPS; acc = fmaf(d, d, acc);   // torch eps convention
        d = a0.y - b0.y + EPS; acc = fmaf(d, d, acc);
        d = a0.z - b0.z + EPS; acc = fmaf(d, d, acc);
        d = a0.w - b0.w + EPS; acc = fmaf(d, d, acc);
        d = a1.x - b1.x + EPS; acc = fmaf(d, d, acc);
        d = a1.y - b1.y + EPS; acc = fmaf(d, d, acc);
        d = a1.z - b1.z + EPS; acc = fmaf(d, d, acc);
        d = a1.w - b1.w + EPS; acc = fmaf(d, d, acc);
        d = a2.x - b2.x + EPS; acc = fmaf(d, d, acc);
        d = a2.y - b2.y + EPS; acc = fmaf(d, d, acc);
        d = a2.z - b2.z + EPS; acc = fmaf(d, d, acc);
        d = a2.w - b2.w + EPS; acc = fmaf(d, d, acc);
        d = a3.x - b3.x + EPS; acc = fmaf(d, d, acc);
        d = a3.y - b3.y + EPS; acc = fmaf(d, d, acc);
        d = a3.z - b3.z + EPS; acc = fmaf(d, d, acc);
        d = a3.w - b3.w + EPS; acc = fmaf(d, d, acc);
        acc = warp_sum(acc);
        if (lane == 0) s_distc[m] = sqrtf(acc);
    }
    __syncthreads();

    // ---- warp 0: full hinge (npos*nneg terms) + 2-level atomic finalize ----
    if (wid == 0) {
        float acc = 0.0f;
        const int npair = npos * nneg;
        for (int p = lane; p < npair; p += 32) {
            const int a = p / nneg;          // positive ordinal
            const int q = p - a * nneg;      // negative ordinal
            acc += fmaxf(s_distc[a] - s_distc[npos + q] + MARGIN, 0.0f);
        }
        acc = warp_sum(acc);

        if (lane == 0) {
            float contrib = 0.0f;
            if (npair > 0) contrib = acc / (float)npair * (1.0f / (float)N);

            // Level 1: fixed-point contrib + arrival count, one atomic per
            // block, 8 slots on distinct L2 lines (48-way contention each).
            const unsigned long long fix =
                (unsigned long long)((double)contrib * FIX_SCALE + 0.5);
            const int slot = i & (NSLOT - 1);
            const unsigned long long add1 = (1ull << CNT_SHIFT) + fix;
            const unsigned long long old1 = atomicAdd(&g_slot[slot * SLOT_PAD], add1);

            if ((old1 >> CNT_SHIFT) == (unsigned long long)(BLOCKS_PER_SLOT - 1)) {
                // Slot winner: forward the complete slot total (sum + count).
                const unsigned long long slot_sum = (old1 + add1) & SUM_MASK;
                const unsigned long long add2 = (1ull << CNT_SHIFT) + slot_sum;
                const unsigned long long old2 = atomicAdd(&g_final, add2);
                if ((old2 >> CNT_SHIFT) == (unsigned long long)(NSLOT - 1)) {
                    // Final winner: write output, reset for graph replay.
                    const unsigned long long total = (old2 + add2) & SUM_MASK;
                    out[0] = (float)((double)total * (1.0 / FIX_SCALE));
                    g_final = 0ull;
#pragma unroll
                    for (int s = 0; s < NSLOT; s++) g_slot[s * SLOT_PAD] = 0ull;
                }
            }
        }
    }
}

extern "C" void kernel_launch(void* const* d_in, const int* in_sizes, int n_in,
                              void* d_out, int out_size) {
    const float* features = (const float*)d_in[0];
    const int*   labels   = (const int*)d_in[1];
    const int*   levels   = (const int*)d_in[2];
    float* out = (float*)d_out;

    triplet_fused_kernel<<<N, BLK>>>(features, labels, levels, out);
}